// round 5
// baseline (speedup 1.0000x reference)
#include <cuda_runtime.h>

// Potts bilateral loss, K=9, PAD=4, sigma_I=0.1, sigma_X=3
// x: [4,3,256,256] f32, y: [4,2,256,256] f32 -> scalar f32
//
// 32x32-output tiles, 256 threads, 4 vertical pixels/thread.
// color term via norm expansion with CI*||w||^2 pre-scaled into smem.
// Per dj, a 12-row register window of all 6 planes is loaded once and
// reused across 4 pixels x 9 di neighbors (2 LDS per neighbor amortized).
// Spatial weight applied via separability: per-di fold with literal g(di),
// per-dj fold with literal g(dj) (no runtime transcendentals in the fold).

#define KS 9
#define TX 32
#define TY 32
#define PY 4
#define SMX (TX + 8)   // 40
#define SMY (TY + 8)   // 40
#define WO 248
#define WW 256
#define PLANE (256 * 256)

#define GX 8
#define GY 8
#define GB 4
#define NBLOCKS (GX * GY * GB)   // 256

__device__ float g_partials[NBLOCKS];

__device__ __forceinline__ float ex2f(float v) {
    float r;
    asm("ex2.approx.ftz.f32 %0, %1;" : "=f"(r) : "f"(v));
    return r;
}

// g(d) = exp(-d*d/9) for d = offset-4, indexed by |offset-4|
__device__ __constant__ float GTAB[5] = {
    1.0f,
    0.894839316818f,   // exp(-1/9)
    0.641180388429f,   // exp(-4/9)
    0.367879441171f,   // exp(-1)
    0.169013315406f    // exp(-16/9)
};

__global__ __launch_bounds__(256, 2) void potts_kernel(
    const float* __restrict__ x, const float* __restrict__ y)
{
    __shared__ float sx0[SMY][SMX];
    __shared__ float sx1[SMY][SMX];
    __shared__ float sx2[SMY][SMX];
    __shared__ float sxn[SMY][SMX];   // CI * ||x||^2 per cell
    __shared__ float sy0[SMY][SMX];
    __shared__ float sy1[SMY][SMX];

    const int b  = blockIdx.z;
    const int ox = blockIdx.x * TX;
    const int oy = blockIdx.y * TY;
    const int tid = threadIdx.x;

    const float L2E = 1.4426950408889634f;   // log2(e)
    const float CI  = -100.0f * L2E;         // -(1/sigma_I^2)*log2(e)

    const float* xb = x + (size_t)b * 3 * PLANE;
    const float* yb = y + (size_t)b * 2 * PLANE;

    // cooperative halo load: float4 fast path where fully in-row, scalar
    // clamped path at the right edge (and bottom rows clamp gr). Clamped
    // cells only feed invalid outputs, whose y-centers are zeroed below.
    for (int i = tid; i < SMY * 10; i += 256) {
        int r  = i / 10;
        int c4 = (i - r * 10) * 4;
        int gr = oy + r; if (gr > 255) gr = 255;
        if (ox + c4 + 3 <= 255) {
            int g = gr * WW + ox + c4;
            float4 a0 = *(const float4*)(xb + g);
            float4 a1 = *(const float4*)(xb + PLANE + g);
            float4 a2 = *(const float4*)(xb + 2 * PLANE + g);
            float4 b0 = *(const float4*)(yb + g);
            float4 b1 = *(const float4*)(yb + PLANE + g);
            *(float4*)&sx0[r][c4] = a0;
            *(float4*)&sx1[r][c4] = a1;
            *(float4*)&sx2[r][c4] = a2;
            *(float4*)&sy0[r][c4] = b0;
            *(float4*)&sy1[r][c4] = b1;
            sxn[r][c4+0] = CI * fmaf(a2.x, a2.x, fmaf(a1.x, a1.x, a0.x*a0.x));
            sxn[r][c4+1] = CI * fmaf(a2.y, a2.y, fmaf(a1.y, a1.y, a0.y*a0.y));
            sxn[r][c4+2] = CI * fmaf(a2.z, a2.z, fmaf(a1.z, a1.z, a0.z*a0.z));
            sxn[r][c4+3] = CI * fmaf(a2.w, a2.w, fmaf(a1.w, a1.w, a0.w*a0.w));
        } else {
            #pragma unroll
            for (int e = 0; e < 4; e++) {
                int gc = ox + c4 + e; if (gc > 255) gc = 255;
                int g  = gr * WW + gc;
                float a0 = xb[g];
                float a1 = xb[PLANE + g];
                float a2 = xb[2 * PLANE + g];
                sx0[r][c4+e] = a0;
                sx1[r][c4+e] = a1;
                sx2[r][c4+e] = a2;
                sxn[r][c4+e] = CI * fmaf(a2, a2, fmaf(a1, a1, a0 * a0));
                sy0[r][c4+e] = yb[g];
                sy1[r][c4+e] = yb[PLANE + g];
            }
        }
    }
    __syncthreads();

    const int lx = tid & 31;
    const int ly = tid >> 5;
    const int rb = ly * PY;
    const bool colok = (ox + lx < WO);

    // per-pixel constants
    float cc0[PY], cc1[PY], cc2[PY], basep[PY], y0c[PY], y1c[PY];
    #pragma unroll
    for (int p = 0; p < PY; p++) {
        int r = rb + p;
        bool ok = colok && (oy + r < WO);
        float c0 = sx0[r + 4][lx + 4];
        float c1 = sx1[r + 4][lx + 4];
        float c2 = sx2[r + 4][lx + 4];
        cc0[p] = -2.0f * CI * c0;
        cc1[p] = -2.0f * CI * c1;
        cc2[p] = -2.0f * CI * c2;
        basep[p] = sxn[r + 4][lx + 4];        // CI * ||c||^2
        y0c[p] = ok ? sy0[r + 4][lx + 4] : 0.f;
        y1c[p] = ok ? sy1[r + 4][lx + 4] : 0.f;
    }

    float total = 0.f;

    #pragma unroll
    for (int dj = 0; dj < KS; dj++) {
        // 12-row register window of all 6 planes at column lx+dj
        float w0[PY + 8], w1[PY + 8], w2[PY + 8];
        float wn[PY + 8], v0[PY + 8], v1[PY + 8];
        #pragma unroll
        for (int k = 0; k < PY + 8; k++) {
            w0[k] = sx0[rb + k][lx + dj];
            w1[k] = sx1[rb + k][lx + dj];
            w2[k] = sx2[rb + k][lx + dj];
            wn[k] = sxn[rb + k][lx + dj];
            v0[k] = sy0[rb + k][lx + dj];
            v1[k] = sy1[rb + k][lx + dj];
        }

        float sdj = 0.f;
        #pragma unroll
        for (int di = 0; di < KS; di++) {
            float t = 0.f;
            #pragma unroll
            for (int p = 0; p < PY; p++) {
                const int k = p + di;
                float arg = fmaf(cc0[p], w0[k],
                            fmaf(cc1[p], w1[k],
                            fmaf(cc2[p], w2[k], wn[k] + basep[p])));
                float E  = ex2f(arg);
                float pr = fmaf(y0c[p], v1[k], y1c[p] * v0[k]);
                t = fmaf(E, pr, t);
            }
            const int ci = (di < 4) ? (4 - di) : (di - 4);
            sdj = fmaf(GTAB[ci], t, sdj);   // g(di) fold (literal)
        }
        const int cj = (dj < 4) ? (4 - dj) : (dj - 4);
        total = fmaf(GTAB[cj], sdj, total); // g(dj) fold (literal)
    }

    // deterministic block reduction
    #pragma unroll
    for (int o = 16; o > 0; o >>= 1)
        total += __shfl_down_sync(0xffffffffu, total, o);

    __shared__ float warpsum[8];
    if (lx == 0) warpsum[ly] = total;
    __syncthreads();
    if (tid == 0) {
        float s = 0.f;
        #pragma unroll
        for (int i = 0; i < 8; i++) s += warpsum[i];
        g_partials[(blockIdx.z * GY + blockIdx.y) * GX + blockIdx.x] = s;
    }
}

__global__ void reduce_kernel(float* __restrict__ out)
{
    __shared__ double sm[256];
    double s = 0.0;
    for (int i = threadIdx.x; i < NBLOCKS; i += 256)
        s += (double)g_partials[i];
    sm[threadIdx.x] = s;
    __syncthreads();
    #pragma unroll
    for (int stride = 128; stride > 0; stride >>= 1) {
        if (threadIdx.x < stride) sm[threadIdx.x] += sm[threadIdx.x + stride];
        __syncthreads();
    }
    if (threadIdx.x == 0) {
        // denominator: B * 81 * 248 * 248 = 19927296
        out[0] = (float)(sm[0] / 19927296.0);
    }
}

extern "C" void kernel_launch(void* const* d_in, const int* in_sizes, int n_in,
                              void* d_out, int out_size)
{
    const float* x = (const float*)d_in[0];
    const float* y = (const float*)d_in[1];
    float* out = (float*)d_out;

    dim3 grid(GX, GY, GB);
    potts_kernel<<<grid, 256>>>(x, y);
    reduce_kernel<<<1, 256>>>(out);
}

// round 16
// speedup vs baseline: 1.2542x; 1.2542x over previous
#include <cuda_runtime.h>

// Potts bilateral loss, K=9, PAD=4, sigma_I=0.1, sigma_X=3
// x: [4,3,256,256] f32, y: [4,2,256,256] f32 -> scalar f32
//
// Symmetric half-window formulation: W and pr are symmetric in (center,
// neighbor); sum over 40 half-offsets + center over ALL pixels, weighting
// each pair by m = [a in I] + [b in I] (I = interior 248^2). Interior
// blocks (m==2 everywhere) take a specialized mask-free path. Norm-
// expanded color term, CI*||x||^2 pre-scaled. float2-packed smem planes.
// Fused last-block final reduction.

#define KS 9
#define TX 32
#define TY 32
#define PY 4
#define SMX (TX + 8)   // 40
#define SMY (TY + 8)   // 40
#define WW 256
#define PLANE (256 * 256)

#define GX 8
#define GY 8
#define GB 4
#define NBLOCKS (GX * GY * GB)   // 256

__device__ float g_partials[NBLOCKS];
__device__ int   g_count = 0;

__device__ __forceinline__ float ex2f(float v) {
    float r;
    asm("ex2.approx.ftz.f32 %0, %1;" : "=f"(r) : "f"(v));
    return r;
}

// g(d) = exp(-d*d/9), indexed by |offset|
__device__ __constant__ float GTAB[5] = {
    1.0f,
    0.894839316818f,   // exp(-1/9)
    0.641180388429f,   // exp(-4/9)
    0.367879441171f,   // exp(-1)
    0.169013315406f    // exp(-16/9)
};

template <bool INTERIOR>
__device__ __forceinline__ float tile_sum(
    const float2 (&sA)[SMY][SMX], const float2 (&sB)[SMY][SMX],
    const float2 (&sY)[SMY][SMX], int lx, int rb, int oy, int ox)
{
    const float L2E = 1.4426950408889634f;
    const float CI  = -100.0f * L2E;

    const int ccol = ox + lx;
    const float cok = (ccol >= 4 && ccol < 252) ? 1.f : 0.f;

    float cc0[PY], cc1[PY], cc2[PY], basep[PY], y0c[PY], y1c[PY], ma[PY];
    #pragma unroll
    for (int p = 0; p < PY; p++) {
        float2 a  = sA[rb + p + 4][lx + 4];
        float2 bb = sB[rb + p + 4][lx + 4];
        float2 c  = sY[rb + p + 4][lx + 4];
        cc0[p] = -2.0f * CI * a.x;
        cc1[p] = -2.0f * CI * a.y;
        cc2[p] = -2.0f * CI * bb.x;
        basep[p] = bb.y;                       // CI * ||c||^2
        y0c[p] = c.x;
        y1c[p] = c.y;
        if (!INTERIOR) {
            int irow = oy + rb + p;
            ma[p] = (irow >= 4 && irow < 252) ? cok : 0.f;
        } else {
            ma[p] = 1.f;   // unused on the fast path
        }
    }

    float rowok[PY + 4];
    if (!INTERIOR) {
        #pragma unroll
        for (int j = 0; j < PY + 4; j++) {
            int mrow = oy + rb + j;
            rowok[j] = (mrow >= 4 && mrow < 252) ? 1.f : 0.f;
        }
    }

    float total = 0.f;

    #pragma unroll
    for (int dj = 0; dj < KS; dj++) {
        float colok = 1.f;
        if (!INTERIOR) {
            int mcol = ccol + dj - 4;
            colok = (mcol >= 4 && mcol < 252) ? 1.f : 0.f;
        }

        // 8-row window (smem rows rb+4 .. rb+11) at column lx+dj
        float2 wA[PY + 4], wB[PY + 4], wY[PY + 4];
        float  mv[PY + 4];
        #pragma unroll
        for (int j = 0; j < PY + 4; j++) {
            wA[j] = sA[rb + 4 + j][lx + dj];
            wB[j] = sB[rb + 4 + j][lx + dj];
            wY[j] = sY[rb + 4 + j][lx + dj];
            if (!INTERIOR) mv[j] = colok * rowok[j];
        }

        float sdj = 0.f;
        // di' = 1..4 (rows below center), all dj
        #pragma unroll
        for (int dip = 1; dip <= 4; dip++) {
            float t = 0.f;
            #pragma unroll
            for (int p = 0; p < PY; p++) {
                const int j = p + dip;
                float arg = fmaf(cc0[p], wA[j].x,
                            fmaf(cc1[p], wA[j].y,
                            fmaf(cc2[p], wB[j].x, wB[j].y + basep[p])));
                float E   = ex2f(arg);
                float pr2 = fmaf(y0c[p], wY[j].y, y1c[p] * wY[j].x);
                if (INTERIOR) {
                    t = fmaf(E, pr2, t);
                } else {
                    float m = ma[p] + mv[j];
                    t = fmaf(E * m, pr2, t);
                }
            }
            sdj = fmaf(GTAB[dip], t, sdj);
        }
        // di' = 0 row, only dj' > 0 (dj >= 5); g(0) = 1
        if (dj >= 5) {
            float t = 0.f;
            #pragma unroll
            for (int p = 0; p < PY; p++) {
                const int j = p;
                float arg = fmaf(cc0[p], wA[j].x,
                            fmaf(cc1[p], wA[j].y,
                            fmaf(cc2[p], wB[j].x, wB[j].y + basep[p])));
                float E   = ex2f(arg);
                float pr2 = fmaf(y0c[p], wY[j].y, y1c[p] * wY[j].x);
                if (INTERIOR) {
                    t = fmaf(E, pr2, t);
                } else {
                    float m = ma[p] + mv[j];
                    t = fmaf(E * m, pr2, t);
                }
            }
            sdj += t;
        }
        const int cj = (dj < 4) ? (4 - dj) : (dj - 4);
        total = fmaf(GTAB[cj], sdj, total);
    }

    // center offset (d = 0): m * y0 * y1 with m = 2*[a in I], W = 1
    if (INTERIOR) {
        #pragma unroll
        for (int p = 0; p < PY; p++)
            total = fmaf(y0c[p], y1c[p], total);
        total *= 2.0f;    // every pair (and center) carries m = 2
    } else {
        #pragma unroll
        for (int p = 0; p < PY; p++)
            total = fmaf(2.0f * ma[p] * y0c[p], y1c[p], total);
    }
    return total;
}

__global__ __launch_bounds__(256, 2) void potts_kernel(
    const float* __restrict__ x, const float* __restrict__ y,
    float* __restrict__ out)
{
    __shared__ float2 sA[SMY][SMX];   // (x0, x1)
    __shared__ float2 sB[SMY][SMX];   // (x2, CI*||x||^2)
    __shared__ float2 sY[SMY][SMX];   // (y0, y1)

    const int b   = blockIdx.z;
    const int ox  = blockIdx.x * TX;  // image col base of tile
    const int oy  = blockIdx.y * TY;  // image row base of tile
    const int tid = threadIdx.x;

    const float L2E = 1.4426950408889634f;
    const float CI  = -100.0f * L2E;

    const float* xb = x + (size_t)b * 3 * PLANE;
    const float* yb = y + (size_t)b * 2 * PLANE;

    // halo: image rows/cols [oy-4, oy+35] x [ox-4, ox+35], clamped.
    // Clamped cells duplicate border pixels (never interior), so the
    // m-mask zeroes every term that touches them.
    for (int i = tid; i < SMY * 10; i += 256) {
        int r  = i / 10;
        int c4 = (i - r * 10) * 4;
        int gr = oy - 4 + r; if (gr < 0) gr = 0; if (gr > 255) gr = 255;
        int gc0 = ox - 4 + c4;
        if (gc0 >= 0 && gc0 + 3 <= 255) {
            int g = gr * WW + gc0;
            float4 a0 = *(const float4*)(xb + g);
            float4 a1 = *(const float4*)(xb + PLANE + g);
            float4 a2 = *(const float4*)(xb + 2 * PLANE + g);
            float4 b0 = *(const float4*)(yb + g);
            float4 b1 = *(const float4*)(yb + PLANE + g);
            sA[r][c4+0] = make_float2(a0.x, a1.x);
            sA[r][c4+1] = make_float2(a0.y, a1.y);
            sA[r][c4+2] = make_float2(a0.z, a1.z);
            sA[r][c4+3] = make_float2(a0.w, a1.w);
            sB[r][c4+0] = make_float2(a2.x, CI * fmaf(a2.x, a2.x, fmaf(a1.x, a1.x, a0.x*a0.x)));
            sB[r][c4+1] = make_float2(a2.y, CI * fmaf(a2.y, a2.y, fmaf(a1.y, a1.y, a0.y*a0.y)));
            sB[r][c4+2] = make_float2(a2.z, CI * fmaf(a2.z, a2.z, fmaf(a1.z, a1.z, a0.z*a0.z)));
            sB[r][c4+3] = make_float2(a2.w, CI * fmaf(a2.w, a2.w, fmaf(a1.w, a1.w, a0.w*a0.w)));
            sY[r][c4+0] = make_float2(b0.x, b1.x);
            sY[r][c4+1] = make_float2(b0.y, b1.y);
            sY[r][c4+2] = make_float2(b0.z, b1.z);
            sY[r][c4+3] = make_float2(b0.w, b1.w);
        } else {
            #pragma unroll
            for (int e = 0; e < 4; e++) {
                int gc = ox - 4 + c4 + e;
                if (gc < 0) gc = 0; if (gc > 255) gc = 255;
                int g = gr * WW + gc;
                float a0 = xb[g];
                float a1 = xb[PLANE + g];
                float a2 = xb[2 * PLANE + g];
                sA[r][c4+e] = make_float2(a0, a1);
                sB[r][c4+e] = make_float2(a2, CI * fmaf(a2, a2, fmaf(a1, a1, a0 * a0)));
                sY[r][c4+e] = make_float2(yb[g], yb[PLANE + g]);
            }
        }
    }
    __syncthreads();

    const int lx = tid & 31;
    const int ly = tid >> 5;
    const int rb = ly * PY;

    // interior block: every center and every half-window mate is interior
    const bool interior =
        (blockIdx.x >= 1 && blockIdx.x <= 6 && blockIdx.y >= 1 && blockIdx.y <= 6);

    float total = interior
        ? tile_sum<true >(sA, sB, sY, lx, rb, oy, ox)
        : tile_sum<false>(sA, sB, sY, lx, rb, oy, ox);

    // deterministic block reduction
    #pragma unroll
    for (int o = 16; o > 0; o >>= 1)
        total += __shfl_down_sync(0xffffffffu, total, o);

    __shared__ float warpsum[8];
    if (lx == 0) warpsum[ly] = total;
    __syncthreads();

    const int bid = (blockIdx.z * GY + blockIdx.y) * GX + blockIdx.x;
    __shared__ bool is_last;
    if (tid == 0) {
        float s = 0.f;
        #pragma unroll
        for (int i = 0; i < 8; i++) s += warpsum[i];
        g_partials[bid] = s;
        __threadfence();
        int old = atomicAdd(&g_count, 1);
        is_last = (old == NBLOCKS - 1);
    }
    __syncthreads();

    // last block performs the final fixed-order reduction
    if (is_last) {
        __shared__ double sm[256];
        sm[tid] = (double)g_partials[tid];   // NBLOCKS == 256
        __syncthreads();
        #pragma unroll
        for (int stride = 128; stride > 0; stride >>= 1) {
            if (tid < stride) sm[tid] += sm[tid + stride];
            __syncthreads();
        }
        if (tid == 0) {
            // denominator: B * 81 * 248 * 248 = 19927296
            out[0] = (float)(sm[0] / 19927296.0);
            g_count = 0;   // reset for next graph replay
        }
    }
}

extern "C" void kernel_launch(void* const* d_in, const int* in_sizes, int n_in,
                              void* d_out, int out_size)
{
    const float* x = (const float*)d_in[0];
    const float* y = (const float*)d_in[1];
    float* out = (float*)d_out;

    dim3 grid(GX, GY, GB);
    potts_kernel<<<grid, 256>>>(x, y, out);
}